// round 12
// baseline (speedup 1.0000x reference)
#include <cuda_runtime.h>
#include <math.h>
#include <float.h>

#define Tn   512
#define Bn   64
#define En   256
#define Hn   512
#define G4   2048
#define NBLK 128
#define NTHR 256

// Scratch (device globals: the sanctioned alloc-free scratch mechanism)
__device__ float    g_xg[(size_t)Tn * G4 * Bn];  // [t][j][b]  256 MB
__device__ float    g_h[2][Hn * Bn];             // ping-pong, [hidx][b]
__device__ float    g_feat[Hn * Bn];             // [hidx][b]
__device__ unsigned g_count;                     // barrier arrivals (self-resetting)
__device__ unsigned g_gen;                       // barrier generation (free-running)

// ---------------------------------------------------------------------------
// Scoped memory ops (cross-SM data traffic is L2-scoped: STG + cp.async.cg,
// so gpu-scope acquire/release suffices — no full MEMBAR / L1 flush needed).
// ---------------------------------------------------------------------------
__device__ __forceinline__ unsigned ld_relaxed_gpu(const unsigned* p) {
    unsigned v;
    asm volatile("ld.relaxed.gpu.global.u32 %0, [%1];" : "=r"(v) : "l"(p));
    return v;
}
__device__ __forceinline__ unsigned ld_acquire_gpu(const unsigned* p) {
    unsigned v;
    asm volatile("ld.acquire.gpu.global.u32 %0, [%1];" : "=r"(v) : "l"(p));
    return v;
}
__device__ __forceinline__ unsigned atom_add_release_gpu(unsigned* p, unsigned v) {
    unsigned old;
    asm volatile("atom.add.release.gpu.global.u32 %0, [%1], %2;"
                 : "=r"(old) : "l"(p), "r"(v));
    return old;
}
__device__ __forceinline__ void st_relaxed_gpu(unsigned* p, unsigned v) {
    asm volatile("st.relaxed.gpu.global.u32 [%0], %1;" :: "l"(p), "r"(v));
}
__device__ __forceinline__ void st_release_gpu(unsigned* p, unsigned v) {
    asm volatile("st.release.gpu.global.u32 [%0], %1;" :: "l"(p), "r"(v));
}

__device__ __forceinline__ void cp_async16(void* s, const void* g) {
    unsigned saddr = (unsigned)__cvta_generic_to_shared(s);
    asm volatile("cp.async.cg.shared.global [%0], [%1], 16;"
                 :: "r"(saddr), "l"(g));
}
#define CP_COMMIT() asm volatile("cp.async.commit_group;")
#define CP_WAIT(N)  asm volatile("cp.async.wait_group %0;" :: "n"(N))

// Packed fp32x2 FMA (exact fp32 semantics, 2 MACs per FMA-pipe slot).
__device__ __forceinline__ unsigned long long ffma2(unsigned long long a,
                                                    unsigned long long b,
                                                    unsigned long long c) {
    unsigned long long d;
    asm("fma.rn.f32x2 %0, %1, %2, %3;" : "=l"(d) : "l"(a), "l"(b), "l"(c));
    return d;
}

// Fast, accurate-enough transcendentals (MUFU-based, ~1e-7 rel err).
__device__ __forceinline__ float sigf(float x) {
    return 1.f / (1.f + __expf(-x));
}
__device__ __forceinline__ float tanhf_fast(float x) {
    return 2.f / (1.f + __expf(-2.f * x)) - 1.f;
}

// ---------------------------------------------------------------------------
// Grid-wide generation barrier (all NBLK blocks co-resident).
// ---------------------------------------------------------------------------
__device__ __forceinline__ void grid_barrier() {
    __syncthreads();
    if (threadIdx.x == 0) {
        const unsigned cur = ld_relaxed_gpu(&g_gen);
        if (atom_add_release_gpu(&g_count, 1u) == NBLK - 1) {
            st_relaxed_gpu(&g_count, 0u);
            st_release_gpu(&g_gen, cur + 1u);   // release orders the reset too
        } else {
            while (ld_acquire_gpu(&g_gen) == cur) {}
        }
    }
    __syncthreads();
}

// ---------------------------------------------------------------------------
// Kernel 1: fused embedding gather + input projection GEMM (unchanged).
// ---------------------------------------------------------------------------
__global__ __launch_bounds__(256)
void embed_gemm_kernel(const int*   __restrict__ x,
                       const float* __restrict__ emb,
                       const float* __restrict__ Wih,
                       const float* __restrict__ bih,
                       const float* __restrict__ bhh) {
    __shared__ float sW[32][132];   // [k][j], pad keeps float4 alignment
    __shared__ float sE[32][68];    // [k][b]
    __shared__ int   sTok[Bn];

    const int tid   = threadIdx.x;
    const int jBase = blockIdx.x * 128;
    const int t     = blockIdx.y;

    if (tid < Bn) sTok[tid] = x[tid * Tn + t];
    __syncthreads();

    const int tb = tid & 15;    // b-group (4 batches)
    const int tj = tid >> 4;    // j-group (8 rows)

    float acc[8][4];
#pragma unroll
    for (int jj = 0; jj < 8; ++jj)
#pragma unroll
        for (int bb = 0; bb < 4; ++bb) acc[jj][bb] = 0.f;

    for (int kc = 0; kc < En; kc += 32) {
#pragma unroll
        for (int i = 0; i < 16; ++i) {                 // 128x32 W chunk
            int idx = tid + i * 256;
            int k = idx & 31, j = idx >> 5;
            sW[k][j] = Wih[(size_t)(jBase + j) * En + kc + k];
        }
#pragma unroll
        for (int i = 0; i < 8; ++i) {                  // 64x32 emb chunk (gathered)
            int idx = tid + i * 256;
            int k = idx & 31, b = idx >> 5;
            sE[k][b] = emb[(size_t)sTok[b] * En + kc + k];
        }
        __syncthreads();

#pragma unroll
        for (int k = 0; k < 32; ++k) {
            const float4 ev = *reinterpret_cast<const float4*>(&sE[k][tb * 4]);
            const float4 wa = *reinterpret_cast<const float4*>(&sW[k][tj * 8]);
            const float4 wb = *reinterpret_cast<const float4*>(&sW[k][tj * 8 + 4]);
            const float e4[4] = {ev.x, ev.y, ev.z, ev.w};
            const float w8[8] = {wa.x, wa.y, wa.z, wa.w, wb.x, wb.y, wb.z, wb.w};
#pragma unroll
            for (int jj = 0; jj < 8; ++jj)
#pragma unroll
                for (int bb = 0; bb < 4; ++bb)
                    acc[jj][bb] += w8[jj] * e4[bb];
        }
        __syncthreads();
    }

    float* xg_t = g_xg + (size_t)t * (G4 * Bn);
#pragma unroll
    for (int jj = 0; jj < 8; ++jj) {
        const int j = jBase + tj * 8 + jj;
        const float bias = bih[j] + bhh[j];
        float4 v = make_float4(acc[jj][0] + bias, acc[jj][1] + bias,
                               acc[jj][2] + bias, acc[jj][3] + bias);
        *reinterpret_cast<float4*>(&xg_t[(size_t)j * Bn + tb * 4]) = v;
    }
}

// ---------------------------------------------------------------------------
// Kernel 2: persistent LSTM recurrence + ragged max-pool.
// Staging: R9-proven per-thread cp.async.cg, 4 pipelined 32KB h chunks +
// double-buffered xg prefetch.
// Dot (NEW): thread = (ks in 2, hh in 4, bp in 32); batch-PAIR packing with
// pre-duplicated weights -> per k: LDS.64 h{b0,b1} + 2x LDS.128 w-dup +
// 4 FFMA2 = 7 inst / 8 MACs (was 6/4). Partials redistributed via sP (8KB),
// epilogue thread (hh,b) sums the 2 k-halves; c-state/max-pool in registers.
// Dynamic smem: sH 128KB + sW2 64KB + sXg 8KB + sP 8KB = 208KB
// ---------------------------------------------------------------------------
#define LSTM_SMEM ((Hn * Bn + Hn * 32 + 2 * 16 * Bn + 32 * Bn) * (int)sizeof(float))

__global__ __launch_bounds__(NTHR, 1)
void lstm_kernel(const float* __restrict__ Whh,
                 const int*   __restrict__ length) {
    extern __shared__ float sm[];
    float* sH  = sm;                   // [k][b]                    512*64
    float* sW2 = sH + Hn * Bn;         // [k][hh][g][dup2]          512*32
    float* sXg = sW2 + Hn * 32;        // [2][g][h2][b]             2*16*64
    float* sP  = sXg + 2 * 16 * Bn;    // [(ks*16+hh*4+g)][b]       32*64

    const int tid  = threadIdx.x;
    const int p    = blockIdx.x;
    const int hrow = p * 4;

    // Dot-phase mapping: warp-uniform (ks, hh); bp spans the warp.
    const int ks = tid >> 7;           // k half (0..1)
    const int hh = (tid >> 5) & 3;     // local h index (0..3)
    const int bp = tid & 31;           // batch pair (0..31) -> b = 2bp, 2bp+1

    // Epilogue mapping: thread owns one (h-index, batch) cell.
    const int ehh = tid >> 6;          // local h index (0..3)
    const int eb  = tid & 63;          // batch (0..63)

    // Load this block's 16 W_hh rows, duplicated: sW2[k*32 + hh*8 + g*2 +{0,1}]
#pragma unroll
    for (int r = 0; r < 16; ++r) {
        const int g = r & 3, h2 = r >> 2;
        const float* src = Whh + (size_t)(g * Hn + hrow + h2) * Hn;
        for (int k = tid; k < Hn; k += NTHR) {
            const float v = src[k];
            sW2[k * 32 + h2 * 8 + g * 2 + 0] = v;
            sW2[k * 32 + h2 * 8 + g * 2 + 1] = v;
        }
    }
    // Zero this block's rows of h buffer 0 (fresh state every launch/replay).
    for (int i = tid; i < 4 * Bn; i += NTHR)
        g_h[0][hrow * Bn + i] = 0.f;

    // Prefetch xg slice for t=0 (1 cp.async group left pending into the loop).
    {
        const int r = tid >> 4, seg = tid & 15;     // 16 rows x 16 segs
        const int g = r >> 2, h2 = r & 3;
        const float* src = g_xg + (size_t)(g * Hn + hrow + h2) * Bn + seg * 4;
        cp_async16(&sXg[r * 64 + seg * 4], src);
        CP_COMMIT();
    }

    float c_state = 0.f;
    float maxv    = -FLT_MAX;
    const int mylen = length[eb];

    grid_barrier();   // release covers the h-buffer zeroing

    for (int t = 0; t < Tn; ++t) {
        const float* hsrc = g_h[t & 1];
        float*       hdst = g_h[(t + 1) & 1];
        const float* xgCur = sXg + (t & 1) * (16 * Bn);
        float*       xgNxt = sXg + ((t + 1) & 1) * (16 * Bn);

        // Issue: 4 h-chunk groups (32 KB each) + xg[t+1] prefetch group.
#pragma unroll
        for (int c = 0; c < 4; ++c) {
            const float* gsrc = hsrc + c * (128 * Bn);
            float*       sdst = sH   + c * (128 * Bn);
#pragma unroll
            for (int j = 0; j < 8; ++j) {
                const int i = tid + j * NTHR;       // 2048 16B segs / chunk
                cp_async16(sdst + i * 4, gsrc + i * 4);
            }
            CP_COMMIT();
        }
        {
            const int tn = (t + 1 < Tn) ? t + 1 : t;
            const int r = tid >> 4, seg = tid & 15;
            const int g = r >> 2, h2 = r & 3;
            const float* src = g_xg + (size_t)tn * (G4 * Bn)
                             + (size_t)(g * Hn + hrow + h2) * Bn + seg * 4;
            cp_async16(xgNxt + r * 64 + seg * 4, src);
            CP_COMMIT();
        }

        // Batch-pair accumulators: {b0,b1} per gate.
        unsigned long long aI = 0ull, aF = 0ull, aG = 0ull, aO = 0ull;

        // Pipelined dot: wait chunk c (+ xg[t] on c=0); thread computes only
        // its k half (chunks 2ks, 2ks+1) but passes every sync point.
#pragma unroll
        for (int c = 0; c < 4; ++c) {
            if (c == 0)      { CP_WAIT(4); }   // retires xg[t] + chunk0
            else if (c == 1) { CP_WAIT(3); }
            else if (c == 2) { CP_WAIT(2); }
            else             { CP_WAIT(1); }   // leaves xg[t+1] pending
            __syncthreads();

            if ((c >> 1) == ks) {
                const float* pH = sH  + c * (128 * Bn) + bp * 2;
                const float* pW = sW2 + c * (128 * 32) + hh * 8;
#pragma unroll 8
                for (int k = 0; k < 128; ++k) {
                    const unsigned long long h2v =
                        *reinterpret_cast<const unsigned long long*>(pH + k * Bn);
                    const ulonglong2 w1 =
                        *reinterpret_cast<const ulonglong2*>(pW + k * 32);     // {i,i},{f,f}
                    const ulonglong2 w2 =
                        *reinterpret_cast<const ulonglong2*>(pW + k * 32 + 4); // {g,g},{o,o}
                    aI = ffma2(w1.x, h2v, aI);
                    aF = ffma2(w1.y, h2v, aF);
                    aG = ffma2(w2.x, h2v, aG);
                    aO = ffma2(w2.y, h2v, aO);
                }
            }
        }

        // Redistribute partials: sP[(ks*16 + hh*4 + g)*64 + 2bp] = {b0,b1}.
        {
            float* base = sP + (ks * 16 + hh * 4) * Bn + bp * 2;
            *reinterpret_cast<unsigned long long*>(base + 0 * Bn) = aI;
            *reinterpret_cast<unsigned long long*>(base + 1 * Bn) = aF;
            *reinterpret_cast<unsigned long long*>(base + 2 * Bn) = aG;
            *reinterpret_cast<unsigned long long*>(base + 3 * Bn) = aO;
        }
        __syncthreads();

        // Epilogue: thread (ehh, eb); sum the two k-half partials + xg.
        {
            const float* p0 = sP + (0 * 16 + ehh * 4) * Bn + eb;
            const float* p1 = sP + (1 * 16 + ehh * 4) * Bn + eb;
            const float gi = xgCur[(0 * 4 + ehh) * 64 + eb] + p0[0 * Bn] + p1[0 * Bn];
            const float gf = xgCur[(1 * 4 + ehh) * 64 + eb] + p0[1 * Bn] + p1[1 * Bn];
            const float gg = xgCur[(2 * 4 + ehh) * 64 + eb] + p0[2 * Bn] + p1[2 * Bn];
            const float go = xgCur[(3 * 4 + ehh) * 64 + eb] + p0[3 * Bn] + p1[3 * Bn];
            const float is = sigf(gi);
            const float fs = sigf(gf);
            const float gt = tanhf_fast(gg);
            const float os = sigf(go);
            c_state = fs * c_state + is * gt;
            const float h = os * tanhf_fast(c_state);
            hdst[(hrow + ehh) * Bn + eb] = h;
            if (t < mylen) maxv = fmaxf(maxv, h);
        }
        grid_barrier();   // release-arrive orders the h store
    }

    g_feat[(hrow + ehh) * Bn + eb] = maxv;
}

// ---------------------------------------------------------------------------
// Kernel 3: classifier  out[b][c] = sum_h feat[h][b] * W_cls[c][h] + b_cls[c]
// ---------------------------------------------------------------------------
__global__ void cls_kernel(const float* __restrict__ Wcls,
                           const float* __restrict__ bcls,
                           float* __restrict__ out) {
    const int tid = threadIdx.x;   // 128 threads
    const int b = tid >> 1, c = tid & 1;
    float s = bcls[c];
#pragma unroll 8
    for (int h = 0; h < Hn; ++h)
        s += g_feat[h * Bn + b] * Wcls[c * Hn + h];
    out[b * 2 + c] = s;
}

// ---------------------------------------------------------------------------
extern "C" void kernel_launch(void* const* d_in, const int* in_sizes, int n_in,
                              void* d_out, int out_size) {
    const int*   x      = (const int*)  d_in[0];  // [64,512] int32
    const int*   length = (const int*)  d_in[1];  // [64,1]   int32
    const float* emb    = (const float*)d_in[2];  // [32000,256]
    const float* Wih    = (const float*)d_in[3];  // [2048,256]
    const float* Whh    = (const float*)d_in[4];  // [2048,512]
    const float* bih    = (const float*)d_in[5];  // [2048]
    const float* bhh    = (const float*)d_in[6];  // [2048]
    const float* Wcls   = (const float*)d_in[7];  // [2,512]
    const float* bcls   = (const float*)d_in[8];  // [2]
    float* out = (float*)d_out;                   // [64,2]

    cudaFuncSetAttribute(lstm_kernel,
                         cudaFuncAttributeMaxDynamicSharedMemorySize, LSTM_SMEM);

    embed_gemm_kernel<<<dim3(16, Tn), 256>>>(x, emb, Wih, bih, bhh);
    lstm_kernel<<<NBLK, NTHR, LSTM_SMEM>>>(Whh, length);
    cls_kernel<<<1, 128>>>(Wcls, bcls, out);
    (void)in_sizes; (void)n_in; (void)out_size;
}

// round 13
// speedup vs baseline: 1.0657x; 1.0657x over previous
#include <cuda_runtime.h>
#include <math.h>
#include <float.h>

#define Tn   512
#define Bn   64
#define En   256
#define Hn   512
#define G4   2048
#define NBLK 128
#define NTHR 256
#define NGRP 4
#define GBLK 32            // blocks per group
#define GB   16            // batches per group

// Scratch (device globals: the sanctioned alloc-free scratch mechanism)
__device__ float    g_xg[(size_t)Tn * G4 * Bn];    // [t][j][b]  256 MB
__device__ float    g_h[2][NGRP * Hn * GB];        // ping-pong, [grp][k][bl]
__device__ float    g_feat[Hn * Bn];               // [hidx][b]
__device__ unsigned g_count[NGRP * 32];            // per-group arrivals (padded)
__device__ unsigned g_gen[NGRP * 32];              // per-group generation

// ---------------------------------------------------------------------------
// Scoped memory ops (cross-SM data traffic is L2-scoped: STG + cp.async.cg).
// ---------------------------------------------------------------------------
__device__ __forceinline__ unsigned ld_relaxed_gpu(const unsigned* p) {
    unsigned v;
    asm volatile("ld.relaxed.gpu.global.u32 %0, [%1];" : "=r"(v) : "l"(p));
    return v;
}
__device__ __forceinline__ unsigned ld_acquire_gpu(const unsigned* p) {
    unsigned v;
    asm volatile("ld.acquire.gpu.global.u32 %0, [%1];" : "=r"(v) : "l"(p));
    return v;
}
__device__ __forceinline__ unsigned atom_add_release_gpu(unsigned* p, unsigned v) {
    unsigned old;
    asm volatile("atom.add.release.gpu.global.u32 %0, [%1], %2;"
                 : "=r"(old) : "l"(p), "r"(v));
    return old;
}
__device__ __forceinline__ void st_relaxed_gpu(unsigned* p, unsigned v) {
    asm volatile("st.relaxed.gpu.global.u32 [%0], %1;" :: "l"(p), "r"(v));
}
__device__ __forceinline__ void st_release_gpu(unsigned* p, unsigned v) {
    asm volatile("st.release.gpu.global.u32 [%0], %1;" :: "l"(p), "r"(v));
}

__device__ __forceinline__ void cp_async16(void* s, const void* g) {
    unsigned saddr = (unsigned)__cvta_generic_to_shared(s);
    asm volatile("cp.async.cg.shared.global [%0], [%1], 16;"
                 :: "r"(saddr), "l"(g));
}
#define CP_COMMIT() asm volatile("cp.async.commit_group;")
#define CP_WAIT(N)  asm volatile("cp.async.wait_group %0;" :: "n"(N))

// Fast, accurate-enough transcendentals (MUFU-based, ~1e-7 rel err).
__device__ __forceinline__ float sigf(float x) {
    return 1.f / (1.f + __expf(-x));
}
__device__ __forceinline__ float tanhf_fast(float x) {
    return 2.f / (1.f + __expf(-2.f * x)) - 1.f;
}

// ---------------------------------------------------------------------------
// Per-GROUP generation barrier (32 co-resident blocks per group).
// ---------------------------------------------------------------------------
__device__ __forceinline__ void group_barrier(int grp) {
    __syncthreads();
    if (threadIdx.x == 0) {
        unsigned* cnt = &g_count[grp * 32];
        unsigned* gen = &g_gen[grp * 32];
        const unsigned cur = ld_relaxed_gpu(gen);
        if (atom_add_release_gpu(cnt, 1u) == GBLK - 1) {
            st_relaxed_gpu(cnt, 0u);
            st_release_gpu(gen, cur + 1u);   // release orders the reset too
        } else {
            while (ld_acquire_gpu(gen) == cur) {}
        }
    }
    __syncthreads();
}

// ---------------------------------------------------------------------------
// Kernel 1: fused embedding gather + input projection GEMM (unchanged).
// ---------------------------------------------------------------------------
__global__ __launch_bounds__(256)
void embed_gemm_kernel(const int*   __restrict__ x,
                       const float* __restrict__ emb,
                       const float* __restrict__ Wih,
                       const float* __restrict__ bih,
                       const float* __restrict__ bhh) {
    __shared__ float sW[32][132];   // [k][j], pad keeps float4 alignment
    __shared__ float sE[32][68];    // [k][b]
    __shared__ int   sTok[Bn];

    const int tid   = threadIdx.x;
    const int jBase = blockIdx.x * 128;
    const int t     = blockIdx.y;

    if (tid < Bn) sTok[tid] = x[tid * Tn + t];
    __syncthreads();

    const int tb = tid & 15;    // b-group (4 batches)
    const int tj = tid >> 4;    // j-group (8 rows)

    float acc[8][4];
#pragma unroll
    for (int jj = 0; jj < 8; ++jj)
#pragma unroll
        for (int bb = 0; bb < 4; ++bb) acc[jj][bb] = 0.f;

    for (int kc = 0; kc < En; kc += 32) {
#pragma unroll
        for (int i = 0; i < 16; ++i) {                 // 128x32 W chunk
            int idx = tid + i * 256;
            int k = idx & 31, j = idx >> 5;
            sW[k][j] = Wih[(size_t)(jBase + j) * En + kc + k];
        }
#pragma unroll
        for (int i = 0; i < 8; ++i) {                  // 64x32 emb chunk (gathered)
            int idx = tid + i * 256;
            int k = idx & 31, b = idx >> 5;
            sE[k][b] = emb[(size_t)sTok[b] * En + kc + k];
        }
        __syncthreads();

#pragma unroll
        for (int k = 0; k < 32; ++k) {
            const float4 ev = *reinterpret_cast<const float4*>(&sE[k][tb * 4]);
            const float4 wa = *reinterpret_cast<const float4*>(&sW[k][tj * 8]);
            const float4 wb = *reinterpret_cast<const float4*>(&sW[k][tj * 8 + 4]);
            const float e4[4] = {ev.x, ev.y, ev.z, ev.w};
            const float w8[8] = {wa.x, wa.y, wa.z, wa.w, wb.x, wb.y, wb.z, wb.w};
#pragma unroll
            for (int jj = 0; jj < 8; ++jj)
#pragma unroll
                for (int bb = 0; bb < 4; ++bb)
                    acc[jj][bb] += w8[jj] * e4[bb];
        }
        __syncthreads();
    }

    float* xg_t = g_xg + (size_t)t * (G4 * Bn);
#pragma unroll
    for (int jj = 0; jj < 8; ++jj) {
        const int j = jBase + tj * 8 + jj;
        const float bias = bih[j] + bhh[j];
        float4 v = make_float4(acc[jj][0] + bias, acc[jj][1] + bias,
                               acc[jj][2] + bias, acc[jj][3] + bias);
        *reinterpret_cast<float4*>(&xg_t[(size_t)j * Bn + tb * 4]) = v;
    }
}

// ---------------------------------------------------------------------------
// Kernel 2: persistent LSTM, BATCH-GROUPED: 4 independent groups of 32 blocks,
// each group owns 16 batches. Block = (grp, q): h rows [16q,16q+16) x 16
// batches. Per-step h staging is 32 KB/block (was 128 KB); barriers are
// per-group (32 arrivals, was 128). Dot: thread (hl,bl) owns 4 gates over
// K=512; register-local epilogue; max-pool in registers.
// Dynamic smem: sH[512*16] 32KB + sW[512*64] 128KB + sXg[2][64*16] 8KB = 168KB
// ---------------------------------------------------------------------------
#define LSTM_SMEM ((Hn * GB + Hn * 64 + 2 * 64 * GB) * (int)sizeof(float))

__global__ __launch_bounds__(NTHR, 1)
void lstm_kernel(const float* __restrict__ Whh,
                 const int*   __restrict__ length) {
    extern __shared__ float sm[];
    float* sH  = sm;                   // [k][bl]            512*16
    float* sW  = sH + Hn * GB;         // [k][hl*4+g]        512*64
    float* sXg = sW + Hn * 64;         // [2][g*16+hl][bl]   2*64*16

    const int tid  = threadIdx.x;
    const int grp  = blockIdx.x >> 5;          // group (0..3)
    const int q    = blockIdx.x & 31;          // block-in-group
    const int hrow = q * GB;                   // first owned h index
    const int bbase = grp * GB;                // first owned batch

    const int hl = tid >> 4;           // local h index (0..15)
    const int bl = tid & 15;           // local batch  (0..15)

    // Load this block's 64 W_hh rows: sW[k*64 + hl*4 + g] (one-time).
#pragma unroll
    for (int r = 0; r < 64; ++r) {
        const int g = r & 3, h2 = r >> 2;
        const float* src = Whh + (size_t)(g * Hn + hrow + h2) * Hn;
        for (int k = tid; k < Hn; k += NTHR)
            sW[k * 64 + h2 * 4 + g] = src[k];
    }
    // Zero this block's h slice in buffer 0: rows hrow..hrow+15, 16 batches.
    {
        const int r = tid >> 4, c = tid & 15;  // 16 rows x 16 cols
        g_h[0][(grp * Hn + hrow + r) * GB + c] = 0.f;
    }

    // Prefetch xg slice for t=0: 64 rows (g*16+hl) x 16 batches = 4 KB.
    {
        const int r = tid >> 2, seg = tid & 3;   // 64 rows x 4 segs (16B)
        const int g = r >> 4, h2 = r & 15;
        const float* src = g_xg + (size_t)(g * Hn + hrow + h2) * Bn
                         + bbase + seg * 4;
        cp_async16(&sXg[r * GB + seg * 4], src);
        CP_COMMIT();
    }

    float c_state = 0.f;
    float maxv    = -FLT_MAX;
    const int mylen = length[bbase + bl];

    group_barrier(grp);   // release covers the h-slice zeroing

    for (int t = 0; t < Tn; ++t) {
        const float* hsrc = g_h[t & 1] + grp * (Hn * GB);
        float*       hdst = g_h[(t + 1) & 1] + grp * (Hn * GB);
        const float* xgCur = sXg + (t & 1) * (64 * GB);
        float*       xgNxt = sXg + ((t + 1) & 1) * (64 * GB);

        // Issue: 4 h-chunk groups (8 KB each) + xg[t+1] prefetch group.
#pragma unroll
        for (int c = 0; c < 4; ++c) {
            const float* gsrc = hsrc + c * (128 * GB);
            float*       sdst = sH   + c * (128 * GB);
#pragma unroll
            for (int j = 0; j < 2; ++j) {
                const int i = tid + j * NTHR;      // 512 16B segs / chunk
                cp_async16(sdst + i * 4, gsrc + i * 4);
            }
            CP_COMMIT();
        }
        {
            const int tn = (t + 1 < Tn) ? t + 1 : t;
            const int r = tid >> 2, seg = tid & 3;
            const int g = r >> 4, h2 = r & 15;
            const float* src = g_xg + (size_t)tn * (G4 * Bn)
                             + (size_t)(g * Hn + hrow + h2) * Bn
                             + bbase + seg * 4;
            cp_async16(xgNxt + r * GB + seg * 4, src);
            CP_COMMIT();
        }

        float aI = 0.f, aF = 0.f, aG = 0.f, aO = 0.f;

        // Pipelined dot: wait chunk c (+ xg[t] on c=0), then FMA over it.
#pragma unroll
        for (int c = 0; c < 4; ++c) {
            if (c == 0)      { CP_WAIT(4); }   // retires xg[t] + chunk0
            else if (c == 1) { CP_WAIT(3); }
            else if (c == 2) { CP_WAIT(2); }
            else             { CP_WAIT(1); }   // leaves xg[t+1] pending
            __syncthreads();

            const float* pH = sH + c * (128 * GB) + bl;
            const float* pW = sW + c * (128 * 64) + hl * 4;
#pragma unroll 8
            for (int k = 0; k < 128; ++k) {
                const float  hk = pH[k * GB];                       // 1 line/warp
                const float4 w  = *reinterpret_cast<const float4*>(pW + k * 64);
                aI += w.x * hk;
                aF += w.y * hk;
                aG += w.z * hk;
                aO += w.w * hk;
            }
        }

        // Epilogue: register-local (gate order i,f,g,o); xg layout [g*16+hl][bl].
        {
            const float gi = xgCur[(0 * 16 + hl) * GB + bl] + aI;
            const float gf = xgCur[(1 * 16 + hl) * GB + bl] + aF;
            const float gg = xgCur[(2 * 16 + hl) * GB + bl] + aG;
            const float go = xgCur[(3 * 16 + hl) * GB + bl] + aO;
            const float is = sigf(gi);
            const float fs = sigf(gf);
            const float gt = tanhf_fast(gg);
            const float os = sigf(go);
            c_state = fs * c_state + is * gt;
            const float h = os * tanhf_fast(c_state);
            hdst[(hrow + hl) * GB + bl] = h;
            if (t < mylen) maxv = fmaxf(maxv, h);
        }
        group_barrier(grp);   // release-arrive orders the h store
    }

    g_feat[(hrow + hl) * Bn + bbase + bl] = maxv;
}

// ---------------------------------------------------------------------------
// Kernel 3: classifier  out[b][c] = sum_h feat[h][b] * W_cls[c][h] + b_cls[c]
// ---------------------------------------------------------------------------
__global__ void cls_kernel(const float* __restrict__ Wcls,
                           const float* __restrict__ bcls,
                           float* __restrict__ out) {
    const int tid = threadIdx.x;   // 128 threads
    const int b = tid >> 1, c = tid & 1;
    float s = bcls[c];
#pragma unroll 8
    for (int h = 0; h < Hn; ++h)
        s += g_feat[h * Bn + b] * Wcls[c * Hn + h];
    out[b * 2 + c] = s;
}

// ---------------------------------------------------------------------------
extern "C" void kernel_launch(void* const* d_in, const int* in_sizes, int n_in,
                              void* d_out, int out_size) {
    const int*   x      = (const int*)  d_in[0];  // [64,512] int32
    const int*   length = (const int*)  d_in[1];  // [64,1]   int32
    const float* emb    = (const float*)d_in[2];  // [32000,256]
    const float* Wih    = (const float*)d_in[3];  // [2048,256]
    const float* Whh    = (const float*)d_in[4];  // [2048,512]
    const float* bih    = (const float*)d_in[5];  // [2048]
    const float* bhh    = (const float*)d_in[6];  // [2048]
    const float* Wcls   = (const float*)d_in[7];  // [2,512]
    const float* bcls   = (const float*)d_in[8];  // [2]
    float* out = (float*)d_out;                   // [64,2]

    cudaFuncSetAttribute(lstm_kernel,
                         cudaFuncAttributeMaxDynamicSharedMemorySize, LSTM_SMEM);

    embed_gemm_kernel<<<dim3(16, Tn), 256>>>(x, emb, Wih, bih, bhh);
    lstm_kernel<<<NBLK, NTHR, LSTM_SMEM>>>(Whh, length);
    cls_kernel<<<1, 128>>>(Wcls, bcls, out);
    (void)in_sizes; (void)n_in; (void)out_size;
}

// round 14
// speedup vs baseline: 1.1447x; 1.0742x over previous
#include <cuda_runtime.h>
#include <math.h>
#include <float.h>

#define Tn   512
#define Bn   64
#define En   256
#define Hn   512
#define G4   2048
#define NBLK 128
#define NTHR 256
#define NGRP 4
#define GBLK 32            // blocks per group
#define GB   16            // batches per group

// Scratch (device globals: the sanctioned alloc-free scratch mechanism)
__device__ float    g_xg[(size_t)Tn * G4 * Bn];    // [t][j][b]  256 MB
__device__ float    g_h[2][NGRP * Hn * GB];        // ping-pong, [grp][k][bl]
__device__ float    g_feat[Hn * Bn];               // [hidx][b]
__device__ unsigned g_count[NGRP * 32];            // per-group arrivals (padded)
__device__ unsigned g_gen[NGRP * 32];              // per-group generation

// ---------------------------------------------------------------------------
// Scoped memory ops (cross-SM data traffic is L2-scoped: STG + cp.async.cg).
// ---------------------------------------------------------------------------
__device__ __forceinline__ unsigned ld_relaxed_gpu(const unsigned* p) {
    unsigned v;
    asm volatile("ld.relaxed.gpu.global.u32 %0, [%1];" : "=r"(v) : "l"(p));
    return v;
}
__device__ __forceinline__ unsigned ld_acquire_gpu(const unsigned* p) {
    unsigned v;
    asm volatile("ld.acquire.gpu.global.u32 %0, [%1];" : "=r"(v) : "l"(p));
    return v;
}
__device__ __forceinline__ unsigned atom_add_release_gpu(unsigned* p, unsigned v) {
    unsigned old;
    asm volatile("atom.add.release.gpu.global.u32 %0, [%1], %2;"
                 : "=r"(old) : "l"(p), "r"(v));
    return old;
}
__device__ __forceinline__ void st_relaxed_gpu(unsigned* p, unsigned v) {
    asm volatile("st.relaxed.gpu.global.u32 [%0], %1;" :: "l"(p), "r"(v));
}
__device__ __forceinline__ void st_release_gpu(unsigned* p, unsigned v) {
    asm volatile("st.release.gpu.global.u32 [%0], %1;" :: "l"(p), "r"(v));
}

__device__ __forceinline__ void cp_async16(void* s, const void* g) {
    unsigned saddr = (unsigned)__cvta_generic_to_shared(s);
    asm volatile("cp.async.cg.shared.global [%0], [%1], 16;"
                 :: "r"(saddr), "l"(g));
}
#define CP_COMMIT() asm volatile("cp.async.commit_group;")
#define CP_WAIT(N)  asm volatile("cp.async.wait_group %0;" :: "n"(N))

// Packed fp32x2 ops (exact fp32 semantics).
__device__ __forceinline__ unsigned long long ffma2(unsigned long long a,
                                                    unsigned long long b,
                                                    unsigned long long c) {
    unsigned long long d;
    asm("fma.rn.f32x2 %0, %1, %2, %3;" : "=l"(d) : "l"(a), "l"(b), "l"(c));
    return d;
}
__device__ __forceinline__ unsigned long long addf2(unsigned long long a,
                                                    unsigned long long b) {
    unsigned long long d;
    asm("add.rn.f32x2 %0, %1, %2;" : "=l"(d) : "l"(a), "l"(b));
    return d;
}
__device__ __forceinline__ unsigned long long dup2(float x) {
    unsigned long long d;
    asm("mov.b64 %0, {%1, %1};" : "=l"(d) : "f"(x));
    return d;
}

// Fast, accurate-enough transcendentals (MUFU-based, ~1e-7 rel err).
__device__ __forceinline__ float sigf(float x) {
    return 1.f / (1.f + __expf(-x));
}
__device__ __forceinline__ float tanhf_fast(float x) {
    return 2.f / (1.f + __expf(-2.f * x)) - 1.f;
}

// ---------------------------------------------------------------------------
// Per-GROUP generation barrier (32 co-resident blocks per group).
// ---------------------------------------------------------------------------
__device__ __forceinline__ void group_barrier(int grp) {
    __syncthreads();
    if (threadIdx.x == 0) {
        unsigned* cnt = &g_count[grp * 32];
        unsigned* gen = &g_gen[grp * 32];
        const unsigned cur = ld_relaxed_gpu(gen);
        if (atom_add_release_gpu(cnt, 1u) == GBLK - 1) {
            st_relaxed_gpu(cnt, 0u);
            st_release_gpu(gen, cur + 1u);   // release orders the reset too
        } else {
            while (ld_acquire_gpu(gen) == cur) {}
        }
    }
    __syncthreads();
}

// ---------------------------------------------------------------------------
// Kernel 1: fused embedding gather + input projection GEMM, f32x2 inner loop.
// W_ih stored DUPLICATED in smem ({w,w} pairs); e-pairs come free from the
// float4 bit pattern. Per k: 5 LDS.128 + 16 FFMA2 (was 3 LDS + 32 FFMA).
// ---------------------------------------------------------------------------
#define SWW 264   // floats per k-row of duplicated W (256 + pad), 16B-aligned

__global__ __launch_bounds__(256)
void embed_gemm_kernel(const int*   __restrict__ x,
                       const float* __restrict__ emb,
                       const float* __restrict__ Wih,
                       const float* __restrict__ bih,
                       const float* __restrict__ bhh) {
    __shared__ float sW2[32][SWW];  // [k][j*2 {dup}]
    __shared__ float sE[32][68];    // [k][b]
    __shared__ int   sTok[Bn];

    const int tid   = threadIdx.x;
    const int jBase = blockIdx.x * 128;
    const int t     = blockIdx.y;

    if (tid < Bn) sTok[tid] = x[tid * Tn + t];
    __syncthreads();

    const int tb = tid & 15;    // b-group (4 batches = 2 pairs)
    const int tj = tid >> 4;    // j-group (8 rows)

    unsigned long long acc2[8][2];
#pragma unroll
    for (int jj = 0; jj < 8; ++jj) { acc2[jj][0] = 0ull; acc2[jj][1] = 0ull; }

    for (int kc = 0; kc < En; kc += 32) {
#pragma unroll
        for (int i = 0; i < 16; ++i) {                 // 128x32 W chunk (dup)
            int idx = tid + i * 256;
            int k = idx & 31, j = idx >> 5;
            const float v = Wih[(size_t)(jBase + j) * En + kc + k];
            sW2[k][j * 2 + 0] = v;
            sW2[k][j * 2 + 1] = v;
        }
#pragma unroll
        for (int i = 0; i < 8; ++i) {                  // 64x32 emb chunk (gathered)
            int idx = tid + i * 256;
            int k = idx & 31, b = idx >> 5;
            sE[k][b] = emb[(size_t)sTok[b] * En + kc + k];
        }
        __syncthreads();

#pragma unroll
        for (int k = 0; k < 32; ++k) {
            const ulonglong2 e2 =
                *reinterpret_cast<const ulonglong2*>(&sE[k][tb * 4]);
            const float* wb = &sW2[k][tj * 16];
            const ulonglong2 wd0 = *reinterpret_cast<const ulonglong2*>(wb + 0);
            const ulonglong2 wd1 = *reinterpret_cast<const ulonglong2*>(wb + 4);
            const ulonglong2 wd2 = *reinterpret_cast<const ulonglong2*>(wb + 8);
            const ulonglong2 wd3 = *reinterpret_cast<const ulonglong2*>(wb + 12);
            acc2[0][0] = ffma2(wd0.x, e2.x, acc2[0][0]);
            acc2[0][1] = ffma2(wd0.x, e2.y, acc2[0][1]);
            acc2[1][0] = ffma2(wd0.y, e2.x, acc2[1][0]);
            acc2[1][1] = ffma2(wd0.y, e2.y, acc2[1][1]);
            acc2[2][0] = ffma2(wd1.x, e2.x, acc2[2][0]);
            acc2[2][1] = ffma2(wd1.x, e2.y, acc2[2][1]);
            acc2[3][0] = ffma2(wd1.y, e2.x, acc2[3][0]);
            acc2[3][1] = ffma2(wd1.y, e2.y, acc2[3][1]);
            acc2[4][0] = ffma2(wd2.x, e2.x, acc2[4][0]);
            acc2[4][1] = ffma2(wd2.x, e2.y, acc2[4][1]);
            acc2[5][0] = ffma2(wd2.y, e2.x, acc2[5][0]);
            acc2[5][1] = ffma2(wd2.y, e2.y, acc2[5][1]);
            acc2[6][0] = ffma2(wd3.x, e2.x, acc2[6][0]);
            acc2[6][1] = ffma2(wd3.x, e2.y, acc2[6][1]);
            acc2[7][0] = ffma2(wd3.y, e2.x, acc2[7][0]);
            acc2[7][1] = ffma2(wd3.y, e2.y, acc2[7][1]);
        }
        __syncthreads();
    }

    float* xg_t = g_xg + (size_t)t * (G4 * Bn);
#pragma unroll
    for (int jj = 0; jj < 8; ++jj) {
        const int j = jBase + tj * 8 + jj;
        const float bias = bih[j] + bhh[j];
        float a0, a1, a2, a3;
        asm("mov.b64 {%0, %1}, %2;" : "=f"(a0), "=f"(a1) : "l"(acc2[jj][0]));
        asm("mov.b64 {%0, %1}, %2;" : "=f"(a2), "=f"(a3) : "l"(acc2[jj][1]));
        float4 v = make_float4(a0 + bias, a1 + bias, a2 + bias, a3 + bias);
        *reinterpret_cast<float4*>(&xg_t[(size_t)j * Bn + tb * 4]) = v;
    }
}

// ---------------------------------------------------------------------------
// Kernel 2: persistent LSTM, batch-grouped (4 groups x 32 blocks x 16 batches)
// NEW dot: thread = (ks in 4, hl in 16, bq in 4). Per k: LDS.128 W{i,f,g,o}
// (natural f32x2 pairs, no dup) + LDS.128 h[4b] + 4 dup-movs + 8 FFMA2
// = 16 MACs / 2 crossbar wavefronts (4x fewer wf, 2x fewer FMA-pipe slots).
// 4-way k-split WITHIN each staged chunk (all warps active per chunk);
// partials summed via 16KB sP buffer; epilogue register-local.
// Dynamic smem: sH 32KB + sW 128KB + sXg 8KB + sP 16KB = 184KB
// ---------------------------------------------------------------------------
#define LSTM_SMEM ((Hn * GB + Hn * 64 + 2 * 64 * GB + 4096) * (int)sizeof(float))

__global__ __launch_bounds__(NTHR, 1)
void lstm_kernel(const float* __restrict__ Whh,
                 const int*   __restrict__ length) {
    extern __shared__ float sm[];
    float* sH   = sm;                    // [k][bl]            512*16
    float* sW   = sH + Hn * GB;          // [k][hl*4+g]        512*64
    float* sXg  = sW + Hn * 64;          // [2][g*16+hl][bl]   2*64*16
    float* sPif = sXg + 2 * 64 * GB;     // ull [ks][hl][b]    1024 ull
    float* sPgo = sPif + 2048;           // ull [ks][hl][b]    1024 ull

    const int tid  = threadIdx.x;
    const int grp  = blockIdx.x >> 5;          // group (0..3)
    const int q    = blockIdx.x & 31;          // block-in-group
    const int hrow = q * GB;                   // first owned h index
    const int bbase = grp * GB;                // first owned batch

    // Dot mapping
    const int ks = tid >> 6;           // k quarter within chunk (0..3)
    const int hl = (tid >> 2) & 15;    // local h index (0..15)
    const int bq = tid & 3;            // batch quad (0..3) -> b = 4bq..4bq+3

    // Epilogue mapping
    const int eh = tid >> 4;           // local h index (0..15)
    const int eb = tid & 15;           // local batch  (0..15)

    // Load this block's 64 W_hh rows: sW[k*64 + hl*4 + g] (one-time).
#pragma unroll
    for (int r = 0; r < 64; ++r) {
        const int g = r & 3, h2 = r >> 2;
        const float* src = Whh + (size_t)(g * Hn + hrow + h2) * Hn;
        for (int k = tid; k < Hn; k += NTHR)
            sW[k * 64 + h2 * 4 + g] = src[k];
    }
    // Zero this block's h slice in buffer 0.
    {
        const int r = tid >> 4, c = tid & 15;
        g_h[0][(grp * Hn + hrow + r) * GB + c] = 0.f;
    }

    // Prefetch xg slice for t=0: 64 rows (g*16+hl) x 16 batches = 4 KB.
    {
        const int r = tid >> 2, seg = tid & 3;   // 64 rows x 4 segs (16B)
        const int g = r >> 4, h2 = r & 15;
        const float* src = g_xg + (size_t)(g * Hn + hrow + h2) * Bn
                         + bbase + seg * 4;
        cp_async16(&sXg[r * GB + seg * 4], src);
        CP_COMMIT();
    }

    float c_state = 0.f;
    float maxv    = -FLT_MAX;
    const int mylen = length[bbase + eb];

    group_barrier(grp);   // release covers the h-slice zeroing

    for (int t = 0; t < Tn; ++t) {
        const float* hsrc = g_h[t & 1] + grp * (Hn * GB);
        float*       hdst = g_h[(t + 1) & 1] + grp * (Hn * GB);
        const float* xgCur = sXg + (t & 1) * (64 * GB);
        float*       xgNxt = sXg + ((t + 1) & 1) * (64 * GB);

        // Issue: 4 h-chunk groups (8 KB each) + xg[t+1] prefetch group.
#pragma unroll
        for (int c = 0; c < 4; ++c) {
            const float* gsrc = hsrc + c * (128 * GB);
            float*       sdst = sH   + c * (128 * GB);
#pragma unroll
            for (int j = 0; j < 2; ++j) {
                const int i = tid + j * NTHR;      // 512 16B segs / chunk
                cp_async16(sdst + i * 4, gsrc + i * 4);
            }
            CP_COMMIT();
        }
        {
            const int tn = (t + 1 < Tn) ? t + 1 : t;
            const int r = tid >> 2, seg = tid & 3;
            const int g = r >> 4, h2 = r & 15;
            const float* src = g_xg + (size_t)tn * (G4 * Bn)
                             + (size_t)(g * Hn + hrow + h2) * Bn
                             + bbase + seg * 4;
            cp_async16(xgNxt + r * GB + seg * 4, src);
            CP_COMMIT();
        }

        // 4 batches x {i,f}/{g,o} packed accumulators.
        unsigned long long aIF[4] = {0ull, 0ull, 0ull, 0ull};
        unsigned long long aGO[4] = {0ull, 0ull, 0ull, 0ull};

        // Pipelined dot: every warp works on every chunk (k-split ks inside).
#pragma unroll
        for (int c = 0; c < 4; ++c) {
            if (c == 0)      { CP_WAIT(4); }   // retires xg[t] + chunk0
            else if (c == 1) { CP_WAIT(3); }
            else if (c == 2) { CP_WAIT(2); }
            else             { CP_WAIT(1); }   // leaves xg[t+1] pending
            __syncthreads();

            const float* pH = sH + c * (128 * GB) + ks * (32 * GB) + bq * 4;
            const float* pW = sW + (c * 128 + ks * 32) * 64 + hl * 4;
#pragma unroll 8
            for (int k = 0; k < 32; ++k) {
                const float4 hv = *reinterpret_cast<const float4*>(pH + k * GB);
                const ulonglong2 w2 =
                    *reinterpret_cast<const ulonglong2*>(pW + k * 64);
                const unsigned long long h0 = dup2(hv.x);
                const unsigned long long h1 = dup2(hv.y);
                const unsigned long long h2d = dup2(hv.z);
                const unsigned long long h3 = dup2(hv.w);
                aIF[0] = ffma2(w2.x, h0, aIF[0]);
                aGO[0] = ffma2(w2.y, h0, aGO[0]);
                aIF[1] = ffma2(w2.x, h1, aIF[1]);
                aGO[1] = ffma2(w2.y, h1, aGO[1]);
                aIF[2] = ffma2(w2.x, h2d, aIF[2]);
                aGO[2] = ffma2(w2.y, h2d, aGO[2]);
                aIF[3] = ffma2(w2.x, h3, aIF[3]);
                aGO[3] = ffma2(w2.y, h3, aGO[3]);
            }
        }

        // Store partials: sPif/sPgo ull at [ks][hl][b].
        {
            unsigned long long* pif =
                reinterpret_cast<unsigned long long*>(sPif)
                + (ks * 16 + hl) * 16 + bq * 4;
            unsigned long long* pgo =
                reinterpret_cast<unsigned long long*>(sPgo)
                + (ks * 16 + hl) * 16 + bq * 4;
#pragma unroll
            for (int j = 0; j < 4; ++j) { pif[j] = aIF[j]; pgo[j] = aGO[j]; }
        }
        __syncthreads();

        // Epilogue: thread (eh, eb) sums 4 k-quarter partials (packed adds).
        {
            const unsigned long long* pif =
                reinterpret_cast<const unsigned long long*>(sPif) + eh * 16 + eb;
            const unsigned long long* pgo =
                reinterpret_cast<const unsigned long long*>(sPgo) + eh * 16 + eb;
            unsigned long long sIF = addf2(addf2(pif[0], pif[256]),
                                           addf2(pif[512], pif[768]));
            unsigned long long sGO = addf2(addf2(pgo[0], pgo[256]),
                                           addf2(pgo[512], pgo[768]));
            float ai, af, ag, ao;
            asm("mov.b64 {%0, %1}, %2;" : "=f"(ai), "=f"(af) : "l"(sIF));
            asm("mov.b64 {%0, %1}, %2;" : "=f"(ag), "=f"(ao) : "l"(sGO));
            const float gi = xgCur[(0 * 16 + eh) * GB + eb] + ai;
            const float gf = xgCur[(1 * 16 + eh) * GB + eb] + af;
            const float gg = xgCur[(2 * 16 + eh) * GB + eb] + ag;
            const float go = xgCur[(3 * 16 + eh) * GB + eb] + ao;
            const float is = sigf(gi);
            const float fs = sigf(gf);
            const float gt = tanhf_fast(gg);
            const float os = sigf(go);
            c_state = fs * c_state + is * gt;
            const float h = os * tanhf_fast(c_state);
            hdst[(hrow + eh) * GB + eb] = h;
            if (t < mylen) maxv = fmaxf(maxv, h);
        }
        group_barrier(grp);   // release-arrive orders the h store
    }

    g_feat[(hrow + eh) * Bn + bbase + eb] = maxv;
}

// ---------------------------------------------------------------------------
// Kernel 3: classifier  out[b][c] = sum_h feat[h][b] * W_cls[c][h] + b_cls[c]
// ---------------------------------------------------------------------------
__global__ void cls_kernel(const float* __restrict__ Wcls,
                           const float* __restrict__ bcls,
                           float* __restrict__ out) {
    const int tid = threadIdx.x;   // 128 threads
    const int b = tid >> 1, c = tid & 1;
    float s = bcls[c];
#pragma unroll 8
    for (int h = 0; h < Hn; ++h)
        s += g_feat[h * Bn + b] * Wcls[c * Hn + h];
    out[b * 2 + c] = s;
}

// ---------------------------------------------------------------------------
extern "C" void kernel_launch(void* const* d_in, const int* in_sizes, int n_in,
                              void* d_out, int out_size) {
    const int*   x      = (const int*)  d_in[0];  // [64,512] int32
    const int*   length = (const int*)  d_in[1];  // [64,1]   int32
    const float* emb    = (const float*)d_in[2];  // [32000,256]
    const float* Wih    = (const float*)d_in[3];  // [2048,256]
    const float* Whh    = (const float*)d_in[4];  // [2048,512]
    const float* bih    = (const float*)d_in[5];  // [2048]
    const float* bhh    = (const float*)d_in[6];  // [2048]
    const float* Wcls   = (const float*)d_in[7];  // [2,512]
    const float* bcls   = (const float*)d_in[8];  // [2]
    float* out = (float*)d_out;                   // [64,2]

    cudaFuncSetAttribute(lstm_kernel,
                         cudaFuncAttributeMaxDynamicSharedMemorySize, LSTM_SMEM);

    embed_gemm_kernel<<<dim3(16, Tn), 256>>>(x, emb, Wih, bih, bhh);
    lstm_kernel<<<NBLK, NTHR, LSTM_SMEM>>>(Whh, length);
    cls_kernel<<<1, 128>>>(Wcls, bcls, out);
    (void)in_sizes; (void)n_in; (void)out_size;
}

// round 15
// speedup vs baseline: 1.4460x; 1.2633x over previous
#include <cuda_runtime.h>
#include <math.h>
#include <float.h>

#define Tn   512
#define Bn   64
#define En   256
#define Hn   512
#define G4   2048
#define NBLK 128
#define NTHR 256
#define NGRP 4
#define GBLK 32            // blocks per group
#define GB   16            // batches per group

// Scratch (device globals: the sanctioned alloc-free scratch mechanism)
__device__ float    g_xg[(size_t)Tn * G4 * Bn];    // [t][j][b]  256 MB
__device__ float    g_h[2][NGRP * Hn * GB];        // ping-pong, [grp][k][bl]
__device__ float    g_feat[Hn * Bn];               // [hidx][b]
__device__ unsigned g_count[NGRP * 32];            // per-group arrivals (padded)
__device__ unsigned g_gen[NGRP * 32];              // per-group generation

// ---------------------------------------------------------------------------
// Scoped memory ops (cross-SM data traffic is L2-scoped: STG + cp.async.cg).
// ---------------------------------------------------------------------------
__device__ __forceinline__ unsigned ld_relaxed_gpu(const unsigned* p) {
    unsigned v;
    asm volatile("ld.relaxed.gpu.global.u32 %0, [%1];" : "=r"(v) : "l"(p));
    return v;
}
__device__ __forceinline__ unsigned ld_acquire_gpu(const unsigned* p) {
    unsigned v;
    asm volatile("ld.acquire.gpu.global.u32 %0, [%1];" : "=r"(v) : "l"(p));
    return v;
}
__device__ __forceinline__ unsigned atom_add_release_gpu(unsigned* p, unsigned v) {
    unsigned old;
    asm volatile("atom.add.release.gpu.global.u32 %0, [%1], %2;"
                 : "=r"(old) : "l"(p), "r"(v));
    return old;
}
__device__ __forceinline__ void st_relaxed_gpu(unsigned* p, unsigned v) {
    asm volatile("st.relaxed.gpu.global.u32 [%0], %1;" :: "l"(p), "r"(v));
}
__device__ __forceinline__ void st_release_gpu(unsigned* p, unsigned v) {
    asm volatile("st.release.gpu.global.u32 [%0], %1;" :: "l"(p), "r"(v));
}

__device__ __forceinline__ void cp_async16(void* s, const void* g) {
    unsigned saddr = (unsigned)__cvta_generic_to_shared(s);
    asm volatile("cp.async.cg.shared.global [%0], [%1], 16;"
                 :: "r"(saddr), "l"(g));
}
#define CP_COMMIT() asm volatile("cp.async.commit_group;")
#define CP_WAIT(N)  asm volatile("cp.async.wait_group %0;" :: "n"(N))

// Packed fp32x2 ops (exact fp32 semantics).
__device__ __forceinline__ unsigned long long ffma2(unsigned long long a,
                                                    unsigned long long b,
                                                    unsigned long long c) {
    unsigned long long d;
    asm("fma.rn.f32x2 %0, %1, %2, %3;" : "=l"(d) : "l"(a), "l"(b), "l"(c));
    return d;
}
__device__ __forceinline__ unsigned long long addf2(unsigned long long a,
                                                    unsigned long long b) {
    unsigned long long d;
    asm("add.rn.f32x2 %0, %1, %2;" : "=l"(d) : "l"(a), "l"(b));
    return d;
}
__device__ __forceinline__ unsigned long long dup2(float x) {
    unsigned long long d;
    asm("mov.b64 %0, {%1, %1};" : "=l"(d) : "f"(x));
    return d;
}

// Fast, accurate-enough transcendentals (MUFU-based, ~1e-7 rel err).
__device__ __forceinline__ float sigf(float x) {
    return 1.f / (1.f + __expf(-x));
}
__device__ __forceinline__ float tanhf_fast(float x) {
    return 2.f / (1.f + __expf(-2.f * x)) - 1.f;
}

// ---------------------------------------------------------------------------
// Per-GROUP generation barrier (32 co-resident blocks per group).
// ---------------------------------------------------------------------------
__device__ __forceinline__ void group_barrier(int grp) {
    __syncthreads();
    if (threadIdx.x == 0) {
        unsigned* cnt = &g_count[grp * 32];
        unsigned* gen = &g_gen[grp * 32];
        const unsigned cur = ld_relaxed_gpu(gen);
        if (atom_add_release_gpu(cnt, 1u) == GBLK - 1) {
            st_relaxed_gpu(cnt, 0u);
            st_release_gpu(gen, cur + 1u);   // release orders the reset too
        } else {
            while (ld_acquire_gpu(gen) == cur) {}
        }
    }
    __syncthreads();
}

// ---------------------------------------------------------------------------
// Kernel 1: fused embedding gather + input projection GEMM — R13 scalar
// version (REVERTED from f32x2: the duplicated-W smem halved occupancy and
// made this kernel ~2x slower; scalar @ 26KB smem runs 2 blocks/SM).
//   xg[t][j][b] = sum_e emb[x[b,t]][e] * W_ih[j][e] + (b_ih[j] + b_hh[j])
// Grid: (16 j-tiles of 128, 512 t), block 256 threads, tile 128x64, BK=32.
// ---------------------------------------------------------------------------
__global__ __launch_bounds__(256)
void embed_gemm_kernel(const int*   __restrict__ x,
                       const float* __restrict__ emb,
                       const float* __restrict__ Wih,
                       const float* __restrict__ bih,
                       const float* __restrict__ bhh) {
    __shared__ float sW[32][132];   // [k][j], pad keeps float4 alignment
    __shared__ float sE[32][68];    // [k][b]
    __shared__ int   sTok[Bn];

    const int tid   = threadIdx.x;
    const int jBase = blockIdx.x * 128;
    const int t     = blockIdx.y;

    if (tid < Bn) sTok[tid] = x[tid * Tn + t];
    __syncthreads();

    const int tb = tid & 15;    // b-group (4 batches)
    const int tj = tid >> 4;    // j-group (8 rows)

    float acc[8][4];
#pragma unroll
    for (int jj = 0; jj < 8; ++jj)
#pragma unroll
        for (int bb = 0; bb < 4; ++bb) acc[jj][bb] = 0.f;

    for (int kc = 0; kc < En; kc += 32) {
#pragma unroll
        for (int i = 0; i < 16; ++i) {                 // 128x32 W chunk
            int idx = tid + i * 256;
            int k = idx & 31, j = idx >> 5;
            sW[k][j] = Wih[(size_t)(jBase + j) * En + kc + k];
        }
#pragma unroll
        for (int i = 0; i < 8; ++i) {                  // 64x32 emb chunk (gathered)
            int idx = tid + i * 256;
            int k = idx & 31, b = idx >> 5;
            sE[k][b] = emb[(size_t)sTok[b] * En + kc + k];
        }
        __syncthreads();

#pragma unroll
        for (int k = 0; k < 32; ++k) {
            const float4 ev = *reinterpret_cast<const float4*>(&sE[k][tb * 4]);
            const float4 wa = *reinterpret_cast<const float4*>(&sW[k][tj * 8]);
            const float4 wb = *reinterpret_cast<const float4*>(&sW[k][tj * 8 + 4]);
            const float e4[4] = {ev.x, ev.y, ev.z, ev.w};
            const float w8[8] = {wa.x, wa.y, wa.z, wa.w, wb.x, wb.y, wb.z, wb.w};
#pragma unroll
            for (int jj = 0; jj < 8; ++jj)
#pragma unroll
                for (int bb = 0; bb < 4; ++bb)
                    acc[jj][bb] += w8[jj] * e4[bb];
        }
        __syncthreads();
    }

    float* xg_t = g_xg + (size_t)t * (G4 * Bn);
#pragma unroll
    for (int jj = 0; jj < 8; ++jj) {
        const int j = jBase + tj * 8 + jj;
        const float bias = bih[j] + bhh[j];
        float4 v = make_float4(acc[jj][0] + bias, acc[jj][1] + bias,
                               acc[jj][2] + bias, acc[jj][3] + bias);
        *reinterpret_cast<float4*>(&xg_t[(size_t)j * Bn + tb * 4]) = v;
    }
}

// ---------------------------------------------------------------------------
// Kernel 2: persistent LSTM, batch-grouped (4 groups x 32 blocks x 16 batches)
// — R14 winner, UNCHANGED. Dot: thread = (ks in 4, hl in 16, bq in 4).
// Per k: LDS.128 W{i,f,g,o} + LDS.128 h[4b] + 4 dup-movs + 8 FFMA2 =
// 16 MACs / 2 crossbar wavefronts. 4-way k-split within each staged chunk;
// partials via 16KB sP; register-local epilogue + max-pool.
// Dynamic smem: sH 32KB + sW 128KB + sXg 8KB + sP 16KB = 184KB
// ---------------------------------------------------------------------------
#define LSTM_SMEM ((Hn * GB + Hn * 64 + 2 * 64 * GB + 4096) * (int)sizeof(float))

__global__ __launch_bounds__(NTHR, 1)
void lstm_kernel(const float* __restrict__ Whh,
                 const int*   __restrict__ length) {
    extern __shared__ float sm[];
    float* sH   = sm;                    // [k][bl]            512*16
    float* sW   = sH + Hn * GB;          // [k][hl*4+g]        512*64
    float* sXg  = sW + Hn * 64;          // [2][g*16+hl][bl]   2*64*16
    float* sPif = sXg + 2 * 64 * GB;     // ull [ks][hl][b]    1024 ull
    float* sPgo = sPif + 2048;           // ull [ks][hl][b]    1024 ull

    const int tid  = threadIdx.x;
    const int grp  = blockIdx.x >> 5;          // group (0..3)
    const int q    = blockIdx.x & 31;          // block-in-group
    const int hrow = q * GB;                   // first owned h index
    const int bbase = grp * GB;                // first owned batch

    // Dot mapping
    const int ks = tid >> 6;           // k quarter within chunk (0..3)
    const int hl = (tid >> 2) & 15;    // local h index (0..15)
    const int bq = tid & 3;            // batch quad (0..3) -> b = 4bq..4bq+3

    // Epilogue mapping
    const int eh = tid >> 4;           // local h index (0..15)
    const int eb = tid & 15;           // local batch  (0..15)

    // Load this block's 64 W_hh rows: sW[k*64 + hl*4 + g] (one-time).
#pragma unroll
    for (int r = 0; r < 64; ++r) {
        const int g = r & 3, h2 = r >> 2;
        const float* src = Whh + (size_t)(g * Hn + hrow + h2) * Hn;
        for (int k = tid; k < Hn; k += NTHR)
            sW[k * 64 + h2 * 4 + g] = src[k];
    }
    // Zero this block's h slice in buffer 0.
    {
        const int r = tid >> 4, c = tid & 15;
        g_h[0][(grp * Hn + hrow + r) * GB + c] = 0.f;
    }

    // Prefetch xg slice for t=0: 64 rows (g*16+hl) x 16 batches = 4 KB.
    {
        const int r = tid >> 2, seg = tid & 3;   // 64 rows x 4 segs (16B)
        const int g = r >> 4, h2 = r & 15;
        const float* src = g_xg + (size_t)(g * Hn + hrow + h2) * Bn
                         + bbase + seg * 4;
        cp_async16(&sXg[r * GB + seg * 4], src);
        CP_COMMIT();
    }

    float c_state = 0.f;
    float maxv    = -FLT_MAX;
    const int mylen = length[bbase + eb];

    group_barrier(grp);   // release covers the h-slice zeroing

    for (int t = 0; t < Tn; ++t) {
        const float* hsrc = g_h[t & 1] + grp * (Hn * GB);
        float*       hdst = g_h[(t + 1) & 1] + grp * (Hn * GB);
        const float* xgCur = sXg + (t & 1) * (64 * GB);
        float*       xgNxt = sXg + ((t + 1) & 1) * (64 * GB);

        // Issue: 4 h-chunk groups (8 KB each) + xg[t+1] prefetch group.
#pragma unroll
        for (int c = 0; c < 4; ++c) {
            const float* gsrc = hsrc + c * (128 * GB);
            float*       sdst = sH   + c * (128 * GB);
#pragma unroll
            for (int j = 0; j < 2; ++j) {
                const int i = tid + j * NTHR;      // 512 16B segs / chunk
                cp_async16(sdst + i * 4, gsrc + i * 4);
            }
            CP_COMMIT();
        }
        {
            const int tn = (t + 1 < Tn) ? t + 1 : t;
            const int r = tid >> 2, seg = tid & 3;
            const int g = r >> 4, h2 = r & 15;
            const float* src = g_xg + (size_t)tn * (G4 * Bn)
                             + (size_t)(g * Hn + hrow + h2) * Bn
                             + bbase + seg * 4;
            cp_async16(xgNxt + r * GB + seg * 4, src);
            CP_COMMIT();
        }

        // 4 batches x {i,f}/{g,o} packed accumulators.
        unsigned long long aIF[4] = {0ull, 0ull, 0ull, 0ull};
        unsigned long long aGO[4] = {0ull, 0ull, 0ull, 0ull};

        // Pipelined dot: every warp works on every chunk (k-split ks inside).
#pragma unroll
        for (int c = 0; c < 4; ++c) {
            if (c == 0)      { CP_WAIT(4); }   // retires xg[t] + chunk0
            else if (c == 1) { CP_WAIT(3); }
            else if (c == 2) { CP_WAIT(2); }
            else             { CP_WAIT(1); }   // leaves xg[t+1] pending
            __syncthreads();

            const float* pH = sH + c * (128 * GB) + ks * (32 * GB) + bq * 4;
            const float* pW = sW + (c * 128 + ks * 32) * 64 + hl * 4;
#pragma unroll 8
            for (int k = 0; k < 32; ++k) {
                const float4 hv = *reinterpret_cast<const float4*>(pH + k * GB);
                const ulonglong2 w2 =
                    *reinterpret_cast<const ulonglong2*>(pW + k * 64);
                const unsigned long long h0 = dup2(hv.x);
                const unsigned long long h1 = dup2(hv.y);
                const unsigned long long h2d = dup2(hv.z);
                const unsigned long long h3 = dup2(hv.w);
                aIF[0] = ffma2(w2.x, h0, aIF[0]);
                aGO[0] = ffma2(w2.y, h0, aGO[0]);
                aIF[1] = ffma2(w2.x, h1, aIF[1]);
                aGO[1] = ffma2(w2.y, h1, aGO[1]);
                aIF[2] = ffma2(w2.x, h2d, aIF[2]);
                aGO[2] = ffma2(w2.y, h2d, aGO[2]);
                aIF[3] = ffma2(w2.x, h3, aIF[3]);
                aGO[3] = ffma2(w2.y, h3, aGO[3]);
            }
        }

        // Store partials: sPif/sPgo ull at [ks][hl][b].
        {
            unsigned long long* pif =
                reinterpret_cast<unsigned long long*>(sPif)
                + (ks * 16 + hl) * 16 + bq * 4;
            unsigned long long* pgo =
                reinterpret_cast<unsigned long long*>(sPgo)
                + (ks * 16 + hl) * 16 + bq * 4;
#pragma unroll
            for (int j = 0; j < 4; ++j) { pif[j] = aIF[j]; pgo[j] = aGO[j]; }
        }
        __syncthreads();

        // Epilogue: thread (eh, eb) sums 4 k-quarter partials (packed adds).
        {
            const unsigned long long* pif =
                reinterpret_cast<const unsigned long long*>(sPif) + eh * 16 + eb;
            const unsigned long long* pgo =
                reinterpret_cast<const unsigned long long*>(sPgo) + eh * 16 + eb;
            unsigned long long sIF = addf2(addf2(pif[0], pif[256]),
                                           addf2(pif[512], pif[768]));
            unsigned long long sGO = addf2(addf2(pgo[0], pgo[256]),
                                           addf2(pgo[512], pgo[768]));
            float ai, af, ag, ao;
            asm("mov.b64 {%0, %1}, %2;" : "=f"(ai), "=f"(af) : "l"(sIF));
            asm("mov.b64 {%0, %1}, %2;" : "=f"(ag), "=f"(ao) : "l"(sGO));
            const float gi = xgCur[(0 * 16 + eh) * GB + eb] + ai;
            const float gf = xgCur[(1 * 16 + eh) * GB + eb] + af;
            const float gg = xgCur[(2 * 16 + eh) * GB + eb] + ag;
            const float go = xgCur[(3 * 16 + eh) * GB + eb] + ao;
            const float is = sigf(gi);
            const float fs = sigf(gf);
            const float gt = tanhf_fast(gg);
            const float os = sigf(go);
            c_state = fs * c_state + is * gt;
            const float h = os * tanhf_fast(c_state);
            hdst[(hrow + eh) * GB + eb] = h;
            if (t < mylen) maxv = fmaxf(maxv, h);
        }
        group_barrier(grp);   // release-arrive orders the h store
    }

    g_feat[(hrow + eh) * Bn + bbase + eb] = maxv;
}

// ---------------------------------------------------------------------------
// Kernel 3: classifier  out[b][c] = sum_h feat[h][b] * W_cls[c][h] + b_cls[c]
// ---------------------------------------------------------------------------
__global__ void cls_kernel(const float* __restrict__ Wcls,
                           const float* __restrict__ bcls,
                           float* __restrict__ out) {
    const int tid = threadIdx.x;   // 128 threads
    const int b = tid >> 1, c = tid & 1;
    float s = bcls[c];
#pragma unroll 8
    for (int h = 0; h < Hn; ++h)
        s += g_feat[h * Bn + b] * Wcls[c * Hn + h];
    out[b * 2 + c] = s;
}

// ---------------------------------------------------------------------------
extern "C" void kernel_launch(void* const* d_in, const int* in_sizes, int n_in,
                              void* d_out, int out_size) {
    const int*   x      = (const int*)  d_in[0];  // [64,512] int32
    const int*   length = (const int*)  d_in[1];  // [64,1]   int32
    const float* emb    = (const float*)d_in[2];  // [32000,256]
    const float* Wih    = (const float*)d_in[3];  // [2048,256]
    const float* Whh    = (const float*)d_in[4];  // [2048,512]
    const float* bih    = (const float*)d_in[5];  // [2048]
    const float* bhh    = (const float*)d_in[6];  // [2048]
    const float* Wcls   = (const float*)d_in[7];  // [2,512]
    const float* bcls   = (const float*)d_in[8];  // [2]
    float* out = (float*)d_out;                   // [64,2]

    cudaFuncSetAttribute(lstm_kernel,
                         cudaFuncAttributeMaxDynamicSharedMemorySize, LSTM_SMEM);

    embed_gemm_kernel<<<dim3(16, Tn), 256>>>(x, emb, Wih, bih, bhh);
    lstm_kernel<<<NBLK, NTHR, LSTM_SMEM>>>(Whh, length);
    cls_kernel<<<1, 128>>>(Wcls, bcls, out);
    (void)in_sizes; (void)n_in; (void)out_size;
}